// round 1
// baseline (speedup 1.0000x reference)
#include <cuda_runtime.h>
#include <math.h>

#define DM   1024
#define DI   2048
#define DS   16
#define DTR  64
#define BB   8
#define LL   1024
#define BT   (BB*LL)        /* 8192 rows */

/* ---------------- scratch (device globals; no allocation allowed) -------- */
__device__ float g_xz  [BT * 4096];   /* in_proj output [8192,4096]; reused for FFN hidden */
__device__ float g_u   [BT * DI];     /* conv+silu output                                  */
__device__ float g_xdbl[BT * 96];     /* x_proj output (dt|B|C)                            */
__device__ float g_dl  [BT * DI];     /* delta; overwritten in-place by gated scan output  */
__device__ float g_m   [BT * DM];     /* mamba block output (residual for FFN)             */
__device__ float g_sums[16];          /* per-batch sum / sumsq                             */

/* ---------------- generic SGEMM: C = epi(A[M,K] @ B[N,K]^T) -------------- */
#define GBM 128
#define GBN 128
#define GBK 8
#define GTM 8
#define GTN 8

#define EPI_NONE     0
#define EPI_SOFTPLUS 1
#define EPI_GELU     2
#define EPI_ADDRES   3

template<int EPI>
__global__ __launch_bounds__(256)
void sgemm(const float* __restrict__ A, int lda,
           const float* __restrict__ Bw, int ldb,
           float* __restrict__ C, int ldc,
           int M, int N, int K,
           const float* __restrict__ bias,
           const float* __restrict__ resid, int ldr)
{
    __shared__ float As[GBK][GBM];
    __shared__ float Bs[GBK][GBN];

    const int tid  = threadIdx.x;
    const int lrow = tid >> 1;            /* 0..127 */
    const int lcol = (tid & 1) * 4;       /* 0 or 4 */
    const int tr   = tid >> 4;            /* 0..15  */
    const int tc   = tid & 15;            /* 0..15  */
    const int gm   = blockIdx.y * GBM;
    const int gn   = blockIdx.x * GBN;

    float acc[GTM][GTN];
#pragma unroll
    for (int i = 0; i < GTM; i++)
#pragma unroll
        for (int j = 0; j < GTN; j++) acc[i][j] = 0.f;

    for (int k0 = 0; k0 < K; k0 += GBK) {
        float4 av = make_float4(0.f, 0.f, 0.f, 0.f);
        float4 bv = make_float4(0.f, 0.f, 0.f, 0.f);
        int ga = gm + lrow;
        if (ga < M) av = *(const float4*)(A  + (size_t)ga * lda + k0 + lcol);
        int gb = gn + lrow;
        if (gb < N) bv = *(const float4*)(Bw + (size_t)gb * ldb + k0 + lcol);

        As[lcol + 0][lrow] = av.x; As[lcol + 1][lrow] = av.y;
        As[lcol + 2][lrow] = av.z; As[lcol + 3][lrow] = av.w;
        Bs[lcol + 0][lrow] = bv.x; Bs[lcol + 1][lrow] = bv.y;
        Bs[lcol + 2][lrow] = bv.z; Bs[lcol + 3][lrow] = bv.w;
        __syncthreads();

#pragma unroll
        for (int k = 0; k < GBK; k++) {
            float ar[GTM], br[GTN];
#pragma unroll
            for (int i = 0; i < GTM; i++) ar[i] = As[k][tr * GTM + i];
#pragma unroll
            for (int j = 0; j < GTN; j++) br[j] = Bs[k][tc * GTN + j];
#pragma unroll
            for (int i = 0; i < GTM; i++)
#pragma unroll
                for (int j = 0; j < GTN; j++)
                    acc[i][j] = fmaf(ar[i], br[j], acc[i][j]);
        }
        __syncthreads();
    }

#pragma unroll
    for (int i = 0; i < GTM; i++) {
        int row = gm + tr * GTM + i;
        if (row >= M) continue;
#pragma unroll
        for (int j = 0; j < GTN; j++) {
            int col = gn + tc * GTN + j;
            if (col >= N) continue;
            float v = acc[i][j];
            if (EPI == EPI_SOFTPLUS) {
                v += bias[col];
                v = (v > 20.f) ? v : log1pf(__expf(v));
            } else if (EPI == EPI_GELU) {
                v += bias[col];
                v = 0.5f * v * (1.f + erff(v * 0.70710678118654752f));
            } else if (EPI == EPI_ADDRES) {
                v += bias[col] + resid[(size_t)row * ldr + col];
            }
            C[(size_t)row * ldc + col] = v;
        }
    }
}

/* ---------------- causal depthwise conv (width 4) + SiLU ----------------- */
__global__ void conv_silu_kernel(const float* __restrict__ xz,
                                 const float* __restrict__ w,
                                 const float* __restrict__ bias,
                                 float* __restrict__ u)
{
    int idx = blockIdx.x * blockDim.x + threadIdx.x;
    if (idx >= BT * DI) return;
    int d  = idx & (DI - 1);
    int bt = idx >> 11;
    int t  = bt & (LL - 1);
    size_t row = (size_t)bt * 4096 + d;   /* xm = xz[:, 0:2048] */

    float w0 = w[d * 4 + 0], w1 = w[d * 4 + 1], w2 = w[d * 4 + 2], w3 = w[d * 4 + 3];
    float acc = bias[d];
    if (t >= 3) acc += xz[row - 3 * 4096] * w0;
    if (t >= 2) acc += xz[row - 2 * 4096] * w1;
    if (t >= 1) acc += xz[row - 1 * 4096] * w2;
    acc += xz[row] * w3;
    u[idx] = acc / (1.f + __expf(-acc));   /* silu */
}

/* ---------------- selective scan + gate --------------------------------- */
/* thread = (b, d). h[16] in registers. yg written in place over delta.      */
__global__ __launch_bounds__(128)
void scan_kernel(const float* __restrict__ u,
                 float* __restrict__ delta_yg,       /* in: delta, out: gated y */
                 const float* __restrict__ xdbl,
                 const float* __restrict__ A_log,
                 const float* __restrict__ Dp,
                 const float* __restrict__ xz)
{
    int d = blockIdx.x * blockDim.x + threadIdx.x;   /* 0..2047 */
    int b = blockIdx.y;                              /* 0..7    */
    if (d >= DI) return;

    float A[DS];
#pragma unroll
    for (int n = 0; n < DS; n++) A[n] = -__expf(A_log[d * DS + n]);
    float Dd = Dp[d];

    float h[DS];
#pragma unroll
    for (int n = 0; n < DS; n++) h[n] = 0.f;

    const float* xd = xdbl + (size_t)b * LL * 96;
    size_t base  = (size_t)b * LL * DI + d;
    size_t rbase = (size_t)b * LL * 4096 + DI + d;   /* res = xz[:, 2048:4096] */

    for (int t = 0; t < LL; t++) {
        float dt  = delta_yg[base + (size_t)t * DI];
        float ut  = u[base + (size_t)t * DI];
        float res = xz[rbase + (size_t)t * 4096];

        const float4* pB = (const float4*)(xd + (size_t)t * 96 + 64);
        const float4* pC = (const float4*)(xd + (size_t)t * 96 + 80);
        float Bv[DS], Cv[DS];
#pragma unroll
        for (int q = 0; q < 4; q++) {
            float4 bq = pB[q], cq = pC[q];
            Bv[q*4+0]=bq.x; Bv[q*4+1]=bq.y; Bv[q*4+2]=bq.z; Bv[q*4+3]=bq.w;
            Cv[q*4+0]=cq.x; Cv[q*4+1]=cq.y; Cv[q*4+2]=cq.z; Cv[q*4+3]=cq.w;
        }

        float y = 0.f;
#pragma unroll
        for (int n = 0; n < DS; n++) {
            float dA = __expf(dt * A[n]);
            h[n] = dA * h[n] + dt * Bv[n] * ut;
            y = fmaf(h[n], Cv[n], y);
        }
        y += ut * Dd;
        float sres = res / (1.f + __expf(-res));
        delta_yg[base + (size_t)t * DI] = y * sres;
    }
}

/* ---------------- LayerNorm over (seq, d_model) per batch ---------------- */
__global__ void ln_zero_kernel() {
    if (threadIdx.x < 16) g_sums[threadIdx.x] = 0.f;
}

__global__ void ln_reduce_kernel(const float* __restrict__ c)
{
    int b = blockIdx.y;
    const float4* p = (const float4*)(c + (size_t)b * (LL * DM));
    const int nvec = (LL * DM) / 4;   /* 262144 */
    float s = 0.f, s2 = 0.f;
    for (int i = blockIdx.x * blockDim.x + threadIdx.x; i < nvec;
         i += gridDim.x * blockDim.x) {
        float4 v = p[i];
        s  += v.x + v.y + v.z + v.w;
        s2 += v.x * v.x + v.y * v.y + v.z * v.z + v.w * v.w;
    }
    __shared__ float ss[256], qq[256];
    int tid = threadIdx.x;
    ss[tid] = s; qq[tid] = s2;
    __syncthreads();
    for (int o = 128; o > 0; o >>= 1) {
        if (tid < o) { ss[tid] += ss[tid + o]; qq[tid] += qq[tid + o]; }
        __syncthreads();
    }
    if (tid == 0) {
        atomicAdd(&g_sums[2 * b + 0], ss[0]);
        atomicAdd(&g_sums[2 * b + 1], qq[0]);
    }
}

__global__ void ln_norm_kernel(float* __restrict__ c)
{
    int b = blockIdx.y;
    const float inv_n = 1.f / (float)(LL * DM);
    float mean = g_sums[2 * b + 0] * inv_n;
    float var  = g_sums[2 * b + 1] * inv_n - mean * mean;
    float is   = rsqrtf(var + 1e-5f);
    float4* p = (float4*)(c + (size_t)b * (LL * DM));
    const int nvec = (LL * DM) / 4;
    for (int i = blockIdx.x * blockDim.x + threadIdx.x; i < nvec;
         i += gridDim.x * blockDim.x) {
        float4 v = p[i];
        v.x = (v.x - mean) * is; v.y = (v.y - mean) * is;
        v.z = (v.z - mean) * is; v.w = (v.w - mean) * is;
        p[i] = v;
    }
}

/* ---------------- host orchestration ------------------------------------ */
extern "C" void kernel_launch(void* const* d_in, const int* in_sizes, int n_in,
                              void* d_out, int out_size)
{
    const float* x         = (const float*)d_in[0];
    const float* in_proj_w = (const float*)d_in[1];
    const float* conv_w    = (const float*)d_in[2];
    const float* conv_b    = (const float*)d_in[3];
    const float* x_proj_w  = (const float*)d_in[4];
    const float* dt_proj_w = (const float*)d_in[5];
    const float* dt_proj_b = (const float*)d_in[6];
    const float* A_log     = (const float*)d_in[7];
    const float* Dp        = (const float*)d_in[8];
    const float* out_proj_w= (const float*)d_in[9];
    const float* ffn_w1    = (const float*)d_in[10];
    const float* ffn_b1    = (const float*)d_in[11];
    const float* ffn_w2    = (const float*)d_in[12];
    const float* ffn_b2    = (const float*)d_in[13];
    float* out = (float*)d_out;

    float *xz, *u, *xdbl, *dl, *m;
    cudaGetSymbolAddress((void**)&xz,   g_xz);
    cudaGetSymbolAddress((void**)&u,    g_u);
    cudaGetSymbolAddress((void**)&xdbl, g_xdbl);
    cudaGetSymbolAddress((void**)&dl,   g_dl);
    cudaGetSymbolAddress((void**)&m,    g_m);

    const int M = BT;

    /* 1. xz = X @ in_proj_w^T              [8192,4096] */
    sgemm<EPI_NONE><<<dim3(4096 / GBN, M / GBM), 256>>>(
        x, DM, in_proj_w, DM, xz, 4096, M, 4096, DM, nullptr, nullptr, 0);

    /* 2. u = silu(causal_conv(xm) + b)     [8192,2048] */
    conv_silu_kernel<<<(BT * DI) / 256, 256>>>(xz, conv_w, conv_b, u);

    /* 3. x_dbl = u @ x_proj_w^T            [8192,96]  */
    sgemm<EPI_NONE><<<dim3(1, M / GBM), 256>>>(
        u, DI, x_proj_w, DI, xdbl, 96, M, 96, DI, nullptr, nullptr, 0);

    /* 4. delta = softplus(dt @ dt_proj_w^T + b)  [8192,2048] */
    sgemm<EPI_SOFTPLUS><<<dim3(DI / GBN, M / GBM), 256>>>(
        xdbl, 96, dt_proj_w, DTR, dl, DI, M, DI, DTR, dt_proj_b, nullptr, 0);

    /* 5. selective scan + u*D + silu(res) gate; in place into dl */
    scan_kernel<<<dim3(DI / 128, BB), 128>>>(u, dl, xdbl, A_log, Dp, xz);

    /* 6. m = yg @ out_proj_w^T             [8192,1024] */
    sgemm<EPI_NONE><<<dim3(DM / GBN, M / GBM), 256>>>(
        dl, DI, out_proj_w, DI, m, DM, M, DM, DI, nullptr, nullptr, 0);

    /* 7. g = gelu(m @ ffn_w1^T + b1)       [8192,4096] (reuse xz) */
    sgemm<EPI_GELU><<<dim3(4096 / GBN, M / GBM), 256>>>(
        m, DM, ffn_w1, DM, xz, 4096, M, 4096, DM, ffn_b1, nullptr, 0);

    /* 8. c = m + g @ ffn_w2^T + b2  -> d_out */
    sgemm<EPI_ADDRES><<<dim3(DM / GBN, M / GBM), 256>>>(
        xz, 4096, ffn_w2, 4096, out, DM, M, DM, 4096, ffn_b2, m, DM);

    /* 9-11. LayerNorm over (seq, d_model) per batch, in place on d_out */
    ln_zero_kernel<<<1, 32>>>();
    ln_reduce_kernel<<<dim3(128, BB), 256>>>(out);
    ln_norm_kernel<<<dim3(128, BB), 256>>>(out);
}

// round 6
// speedup vs baseline: 1.6179x; 1.6179x over previous
#include <cuda_runtime.h>
#include <cuda_bf16.h>
#include <mma.h>
#include <math.h>

using namespace nvcuda;
typedef __nv_bfloat16 bf16;

#define DM   1024
#define DI   2048
#define DS   16
#define DTR  64
#define BB   8
#define LL   1024
#define BT   (BB*LL)

/* ---------------- scratch (device globals; no allocation allowed) -------- */
__device__ __align__(16) float g_xz  [BT * 4096];
__device__ __align__(16) float g_xdbl[BT * 96];
__device__ __align__(16) float g_dl  [BT * DI];
__device__ __align__(16) float g_m   [BT * DM];
__device__ float g_sums[16];

__device__ __align__(16) bf16 g_xhi[BT*DM];
__device__ __align__(16) bf16 g_xlo[BT*DM];
__device__ __align__(16) bf16 g_wihi[4096*DM];
__device__ __align__(16) bf16 g_wilo[4096*DM];
__device__ __align__(16) bf16 g_wxhi[96*DI];
__device__ __align__(16) bf16 g_wxlo[96*DI];
__device__ __align__(16) bf16 g_wdhi[DI*DTR];
__device__ __align__(16) bf16 g_wdlo[DI*DTR];
__device__ __align__(16) bf16 g_wohi[DM*DI];
__device__ __align__(16) bf16 g_wolo[DM*DI];
__device__ __align__(16) bf16 g_w1hi[4096*DM];
__device__ __align__(16) bf16 g_w1lo[4096*DM];
__device__ __align__(16) bf16 g_w2hi[DM*4096];
__device__ __align__(16) bf16 g_w2lo[DM*4096];
__device__ __align__(16) bf16 g_uhi[BT*DI];
__device__ __align__(16) bf16 g_ulo[BT*DI];
__device__ __align__(16) bf16 g_xdhi[BT*96];
__device__ __align__(16) bf16 g_xdlo[BT*96];
__device__ __align__(16) bf16 g_yghi[BT*DI];
__device__ __align__(16) bf16 g_yglo[BT*DI];
__device__ __align__(16) bf16 g_mhi[BT*DM];
__device__ __align__(16) bf16 g_mlo[BT*DM];
__device__ __align__(16) bf16 g_ghi[BT*4096];
__device__ __align__(16) bf16 g_glo[BT*4096];

/* ---------------- bf16 split-GEMM via wmma: C = epi(A @ B^T) ------------- */
#define BMT 128
#define BNT 128
#define BKT 32
#define AST 40

/* OP: 1=in_proj 3=x_proj 4=dt_proj 6=out_proj 7=ffn1 8=ffn2 */
template<int OP>
__global__ __launch_bounds__(256)
void wgemm(float* __restrict__ Cext, const float* __restrict__ bias)
{
    constexpr int NN  = (OP==1)?4096 : (OP==3)?96 : (OP==4)?2048 : (OP==6)?1024 : (OP==7)?4096 : 1024;
    constexpr int KK  = (OP==1)?1024 : (OP==3)?2048 : (OP==4)?64 : (OP==6)?2048 : (OP==7)?1024 : 4096;
    constexpr int LDA = (OP==4) ? 96 : KK;
    constexpr int LDB = KK;
    constexpr int LDC = NN;
    constexpr bool WF32   = (OP != 7);
    constexpr bool WSPLIT = (OP==3 || OP==6 || OP==7);

    const bf16* Ahi;
    const bf16* Alo;
    const bf16* Bhw;
    const bf16* Blw;
    float* C = Cext;
    bf16* Chi = 0;
    bf16* Clo = 0;
    if (OP==1) { Ahi=g_xhi;  Alo=g_xlo;  Bhw=g_wihi; Blw=g_wilo; C=g_xz; }
    if (OP==3) { Ahi=g_uhi;  Alo=g_ulo;  Bhw=g_wxhi; Blw=g_wxlo; C=g_xdbl; Chi=g_xdhi; Clo=g_xdlo; }
    if (OP==4) { Ahi=g_xdhi; Alo=g_xdlo; Bhw=g_wdhi; Blw=g_wdlo; C=g_dl; }
    if (OP==6) { Ahi=g_yghi; Alo=g_yglo; Bhw=g_wohi; Blw=g_wolo; C=g_m; Chi=g_mhi; Clo=g_mlo; }
    if (OP==7) { Ahi=g_mhi;  Alo=g_mlo;  Bhw=g_w1hi; Blw=g_w1lo; Chi=g_ghi; Clo=g_glo; }
    if (OP==8) { Ahi=g_ghi;  Alo=g_glo;  Bhw=g_w2hi; Blw=g_w2lo; }

    __shared__ bf16 Ash[BMT][AST];
    __shared__ bf16 Asl[BMT][AST];
    __shared__ bf16 Bsh[BNT][AST];
    __shared__ bf16 Bsl[BNT][AST];
    __shared__ float stage[8][16][16];

    const int tid  = threadIdx.x;
    const int lane = tid & 31;
    const int warp = tid >> 5;
    const int wm   = warp >> 1;
    const int wn   = warp & 1;
    const int bm   = blockIdx.y * BMT;
    const int bn   = blockIdx.x * BNT;

    wmma::fragment<wmma::accumulator, 16, 16, 16, float> acc[2][4];
    for (int mt = 0; mt < 2; mt++)
        for (int nt = 0; nt < 4; nt++)
            wmma::fill_fragment(acc[mt][nt], 0.0f);

    const int lr = tid >> 1;
    const int lc = (tid & 1) * 16;
    const uint4 zz = make_uint4(0u, 0u, 0u, 0u);

    for (int k0 = 0; k0 < KK; k0 += BKT) {
        __syncthreads();
        {
            const bf16* pah = Ahi + (size_t)(bm + lr) * LDA + k0 + lc;
            const bf16* pal = Alo + (size_t)(bm + lr) * LDA + k0 + lc;
            *(uint4*)&Ash[lr][lc]     = *(const uint4*)(pah);
            *(uint4*)&Ash[lr][lc + 8] = *(const uint4*)(pah + 8);
            *(uint4*)&Asl[lr][lc]     = *(const uint4*)(pal);
            *(uint4*)&Asl[lr][lc + 8] = *(const uint4*)(pal + 8);

            bool bv = (bn + lr) < NN;
            int brow = bv ? (bn + lr) : 0;
            const bf16* pbh = Bhw + (size_t)brow * LDB + k0 + lc;
            const bf16* pbl = Blw + (size_t)brow * LDB + k0 + lc;
            *(uint4*)&Bsh[lr][lc]     = bv ? *(const uint4*)(pbh)     : zz;
            *(uint4*)&Bsh[lr][lc + 8] = bv ? *(const uint4*)(pbh + 8) : zz;
            *(uint4*)&Bsl[lr][lc]     = bv ? *(const uint4*)(pbl)     : zz;
            *(uint4*)&Bsl[lr][lc + 8] = bv ? *(const uint4*)(pbl + 8) : zz;
        }
        __syncthreads();

        for (int kk = 0; kk < BKT; kk += 16) {
            wmma::fragment<wmma::matrix_a, 16, 16, 16, bf16, wmma::row_major> fah[2];
            wmma::fragment<wmma::matrix_a, 16, 16, 16, bf16, wmma::row_major> fal[2];
            for (int mt = 0; mt < 2; mt++) {
                wmma::load_matrix_sync(fah[mt], &Ash[wm * 32 + mt * 16][kk], AST);
                wmma::load_matrix_sync(fal[mt], &Asl[wm * 32 + mt * 16][kk], AST);
            }
            for (int nt = 0; nt < 4; nt++) {
                wmma::fragment<wmma::matrix_b, 16, 16, 16, bf16, wmma::col_major> fbh;
                wmma::fragment<wmma::matrix_b, 16, 16, 16, bf16, wmma::col_major> fbl;
                wmma::load_matrix_sync(fbh, &Bsh[wn * 64 + nt * 16][kk], AST);
                wmma::load_matrix_sync(fbl, &Bsl[wn * 64 + nt * 16][kk], AST);
                for (int mt = 0; mt < 2; mt++) {
                    wmma::mma_sync(acc[mt][nt], fah[mt], fbh, acc[mt][nt]);
                    wmma::mma_sync(acc[mt][nt], fah[mt], fbl, acc[mt][nt]);
                    wmma::mma_sync(acc[mt][nt], fal[mt], fbh, acc[mt][nt]);
                }
            }
        }
    }

    /* --- epilogue: stage each 16x16 tile through smem --- */
    for (int mt = 0; mt < 2; mt++) {
        for (int nt = 0; nt < 4; nt++) {
            __syncwarp();
            wmma::store_matrix_sync(&stage[warp][0][0], acc[mt][nt], 16, wmma::mem_row_major);
            __syncwarp();
            for (int i = 0; i < 8; i++) {
                int idx = i * 32 + lane;
                int rr = idx >> 4;
                int cc = idx & 15;
                int grow = bm + wm * 32 + mt * 16 + rr;
                int gcol = bn + wn * 64 + nt * 16 + cc;
                if (gcol < NN) {
                    float v = stage[warp][rr][cc];
                    if (OP == 4) {
                        v += bias[gcol];
                        v = (v > 20.f) ? v : log1pf(__expf(v));
                    }
                    if (OP == 7) {
                        v += bias[gcol];
                        v = 0.5f * v * (1.f + erff(v * 0.70710678118654752f));
                    }
                    if (OP == 8) {
                        v += bias[gcol] + g_m[(size_t)grow * 1024 + gcol];
                    }
                    if (WF32) {
                        C[(size_t)grow * LDC + gcol] = v;
                    }
                    if (WSPLIT) {
                        bf16 h = __float2bfloat16(v);
                        Chi[(size_t)grow * LDC + gcol] = h;
                        Clo[(size_t)grow * LDC + gcol] = __float2bfloat16(v - __bfloat162float(h));
                    }
                }
            }
        }
    }
}

/* ---------------- fp32 -> bf16 hi/lo split ------------------------------- */
/* W: 0=x 1=in_proj 2=x_proj 3=dt_proj 4=out_proj 5=w1 6=w2 */
template<int W>
__global__ void split_kernel(const float4* __restrict__ src, int n4)
{
    bf16* hi;
    bf16* lo;
    if (W==0) { hi=g_xhi;  lo=g_xlo;  }
    if (W==1) { hi=g_wihi; lo=g_wilo; }
    if (W==2) { hi=g_wxhi; lo=g_wxlo; }
    if (W==3) { hi=g_wdhi; lo=g_wdlo; }
    if (W==4) { hi=g_wohi; lo=g_wolo; }
    if (W==5) { hi=g_w1hi; lo=g_w1lo; }
    if (W==6) { hi=g_w2hi; lo=g_w2lo; }

    int i = blockIdx.x * blockDim.x + threadIdx.x;
    if (i >= n4) return;
    float4 v = src[i];
    float vv[4];
    vv[0] = v.x; vv[1] = v.y; vv[2] = v.z; vv[3] = v.w;
    for (int q = 0; q < 4; q++) {
        bf16 h = __float2bfloat16(vv[q]);
        hi[i * 4 + q] = h;
        lo[i * 4 + q] = __float2bfloat16(vv[q] - __bfloat162float(h));
    }
}

/* ---------------- causal depthwise conv (width 4) + SiLU + split --------- */
__global__ void conv_silu_kernel(const float* __restrict__ w,
                                 const float* __restrict__ bias)
{
    int idx = blockIdx.x * blockDim.x + threadIdx.x;
    if (idx >= BT * DI) return;
    int d  = idx & (DI - 1);
    int bt = idx >> 11;
    int t  = bt & (LL - 1);
    size_t row = (size_t)bt * 4096 + d;

    float w0 = w[d * 4 + 0];
    float w1 = w[d * 4 + 1];
    float w2 = w[d * 4 + 2];
    float w3 = w[d * 4 + 3];
    float acc = bias[d];
    if (t >= 3) acc += g_xz[row - 3 * 4096] * w0;
    if (t >= 2) acc += g_xz[row - 2 * 4096] * w1;
    if (t >= 1) acc += g_xz[row - 1 * 4096] * w2;
    acc += g_xz[row] * w3;
    float uv = acc / (1.f + __expf(-acc));
    bf16 h = __float2bfloat16(uv);
    g_uhi[idx] = h;
    g_ulo[idx] = __float2bfloat16(uv - __bfloat162float(h));
}

/* ---------------- selective scan + gate, bf16-split output --------------- */
__global__ __launch_bounds__(128)
void scan_kernel(const float* __restrict__ A_log,
                 const float* __restrict__ Dp)
{
    int d = blockIdx.x * blockDim.x + threadIdx.x;
    int b = blockIdx.y;
    if (d >= DI) return;

    float A[DS];
    for (int n = 0; n < DS; n++) A[n] = -__expf(A_log[d * DS + n]);
    float Dd = Dp[d];

    float h[DS];
    for (int n = 0; n < DS; n++) h[n] = 0.f;

    const float* xd = g_xdbl + (size_t)b * LL * 96;
    size_t base  = (size_t)b * LL * DI + d;
    size_t rbase = (size_t)b * LL * 4096 + DI + d;

    for (int t = 0; t < LL; t++) {
        size_t off = base + (size_t)t * DI;
        float dt  = g_dl[off];
        float ut  = __bfloat162float(g_uhi[off]) + __bfloat162float(g_ulo[off]);
        float res = g_xz[rbase + (size_t)t * 4096];

        const float4* pB = (const float4*)(xd + (size_t)t * 96 + 64);
        const float4* pC = (const float4*)(xd + (size_t)t * 96 + 80);
        float Bv[DS];
        float Cv[DS];
        for (int q = 0; q < 4; q++) {
            float4 bq = pB[q];
            float4 cq = pC[q];
            Bv[q*4+0]=bq.x; Bv[q*4+1]=bq.y; Bv[q*4+2]=bq.z; Bv[q*4+3]=bq.w;
            Cv[q*4+0]=cq.x; Cv[q*4+1]=cq.y; Cv[q*4+2]=cq.z; Cv[q*4+3]=cq.w;
        }

        float y = 0.f;
        for (int n = 0; n < DS; n++) {
            float dA = __expf(dt * A[n]);
            h[n] = dA * h[n] + dt * Bv[n] * ut;
            y = fmaf(h[n], Cv[n], y);
        }
        y += ut * Dd;
        float sres = res / (1.f + __expf(-res));
        float yg = y * sres;
        bf16 hh = __float2bfloat16(yg);
        g_yghi[off] = hh;
        g_yglo[off] = __float2bfloat16(yg - __bfloat162float(hh));
    }
}

/* ---------------- LayerNorm over (seq, d_model) per batch ---------------- */
__global__ void ln_zero_kernel()
{
    if (threadIdx.x < 16) g_sums[threadIdx.x] = 0.f;
}

__global__ void ln_reduce_kernel(const float* __restrict__ c)
{
    int b = blockIdx.y;
    const float4* p = (const float4*)(c + (size_t)b * (LL * DM));
    const int nvec = (LL * DM) / 4;
    float s = 0.f;
    float s2 = 0.f;
    for (int i = blockIdx.x * blockDim.x + threadIdx.x; i < nvec;
         i += gridDim.x * blockDim.x) {
        float4 v = p[i];
        s  += v.x + v.y + v.z + v.w;
        s2 += v.x * v.x + v.y * v.y + v.z * v.z + v.w * v.w;
    }
    __shared__ float ss[256];
    __shared__ float qq[256];
    int tid = threadIdx.x;
    ss[tid] = s;
    qq[tid] = s2;
    __syncthreads();
    for (int o = 128; o > 0; o >>= 1) {
        if (tid < o) {
            ss[tid] += ss[tid + o];
            qq[tid] += qq[tid + o];
        }
        __syncthreads();
    }
    if (tid == 0) {
        atomicAdd(&g_sums[2 * b + 0], ss[0]);
        atomicAdd(&g_sums[2 * b + 1], qq[0]);
    }
}

__global__ void ln_norm_kernel(float* __restrict__ c)
{
    int b = blockIdx.y;
    const float inv_n = 1.f / (float)(LL * DM);
    float mean = g_sums[2 * b + 0] * inv_n;
    float var  = g_sums[2 * b + 1] * inv_n - mean * mean;
    float is   = rsqrtf(var + 1e-5f);
    float4* p = (float4*)(c + (size_t)b * (LL * DM));
    const int nvec = (LL * DM) / 4;
    for (int i = blockIdx.x * blockDim.x + threadIdx.x; i < nvec;
         i += gridDim.x * blockDim.x) {
        float4 v = p[i];
        v.x = (v.x - mean) * is;
        v.y = (v.y - mean) * is;
        v.z = (v.z - mean) * is;
        v.w = (v.w - mean) * is;
        p[i] = v;
    }
}

/* ---------------- host orchestration ------------------------------------ */
extern "C" void kernel_launch(void* const* d_in, const int* in_sizes, int n_in,
                              void* d_out, int out_size)
{
    const float* x         = (const float*)d_in[0];
    const float* in_proj_w = (const float*)d_in[1];
    const float* conv_w    = (const float*)d_in[2];
    const float* conv_b    = (const float*)d_in[3];
    const float* x_proj_w  = (const float*)d_in[4];
    const float* dt_proj_w = (const float*)d_in[5];
    const float* dt_proj_b = (const float*)d_in[6];
    const float* A_log     = (const float*)d_in[7];
    const float* Dp        = (const float*)d_in[8];
    const float* out_proj_w= (const float*)d_in[9];
    const float* ffn_w1    = (const float*)d_in[10];
    const float* ffn_b1    = (const float*)d_in[11];
    const float* ffn_w2    = (const float*)d_in[12];
    const float* ffn_b2    = (const float*)d_in[13];
    float* out = (float*)d_out;

    /* 0. hi/lo splits of input + weights */
    split_kernel<0><<<(BT*DM/4 + 255)/256, 256>>>((const float4*)x, BT*DM/4);
    split_kernel<1><<<(4096*DM/4 + 255)/256, 256>>>((const float4*)in_proj_w, 4096*DM/4);
    split_kernel<2><<<(96*DI/4 + 255)/256, 256>>>((const float4*)x_proj_w, 96*DI/4);
    split_kernel<3><<<(DI*DTR/4 + 255)/256, 256>>>((const float4*)dt_proj_w, DI*DTR/4);
    split_kernel<4><<<(DM*DI/4 + 255)/256, 256>>>((const float4*)out_proj_w, DM*DI/4);
    split_kernel<5><<<(4096*DM/4 + 255)/256, 256>>>((const float4*)ffn_w1, 4096*DM/4);
    split_kernel<6><<<(DM*4096/4 + 255)/256, 256>>>((const float4*)ffn_w2, DM*4096/4);

    /* 1. xz = X @ in_proj_w^T  [8192,4096] */
    wgemm<1><<<dim3(32, 64), 256>>>(0, 0);

    /* 2. u = silu(conv(xm)+b) -> hi/lo */
    conv_silu_kernel<<<(BT * DI) / 256, 256>>>(conv_w, conv_b);

    /* 3. x_dbl = u @ x_proj_w^T  [8192,96] + split */
    wgemm<3><<<dim3(1, 64), 256>>>(0, 0);

    /* 4. delta = softplus(dt @ dt_proj_w^T + b)  [8192,2048] */
    wgemm<4><<<dim3(16, 64), 256>>>(0, dt_proj_b);

    /* 5. selective scan + gate -> yg hi/lo */
    scan_kernel<<<dim3(DI / 128, BB), 128>>>(A_log, Dp);

    /* 6. m = yg @ out_proj_w^T  [8192,1024] + split */
    wgemm<6><<<dim3(8, 64), 256>>>(0, 0);

    /* 7. g = gelu(m @ ffn_w1^T + b1)  [8192,4096] split only */
    wgemm<7><<<dim3(32, 64), 256>>>(0, ffn_b1);

    /* 8. c = m + g @ ffn_w2^T + b2 -> d_out */
    wgemm<8><<<dim3(8, 64), 256>>>(out, ffn_b2);

    /* 9. LayerNorm per batch, in place on d_out */
    ln_zero_kernel<<<1, 32>>>();
    ln_reduce_kernel<<<dim3(128, BB), 256>>>(out);
    ln_norm_kernel<<<dim3(128, BB), 256>>>(out);
}

// round 7
// speedup vs baseline: 1.6396x; 1.0134x over previous
#include <cuda_runtime.h>
#include <cuda_bf16.h>
#include <cuda_pipeline.h>
#include <mma.h>
#include <math.h>

using namespace nvcuda;
typedef __nv_bfloat16 bf16;

#define DM   1024
#define DI   2048
#define DS   16
#define DTR  64
#define BB   8
#define LL   1024
#define BT   (BB*LL)

/* ---------------- scratch (device globals; no allocation allowed) -------- */
__device__ __align__(16) float g_xz  [BT * 4096];
__device__ __align__(16) float g_xdbl[BT * 96];
__device__ __align__(16) float g_dl  [BT * DI];
__device__ __align__(16) float g_m   [BT * DM];
__device__ float g_sums[16];

__device__ __align__(16) bf16 g_xhi[BT*DM];
__device__ __align__(16) bf16 g_xlo[BT*DM];
__device__ __align__(16) bf16 g_wihi[4096*DM];
__device__ __align__(16) bf16 g_wilo[4096*DM];
__device__ __align__(16) bf16 g_wxhi[96*DI];
__device__ __align__(16) bf16 g_wxlo[96*DI];
__device__ __align__(16) bf16 g_wdhi[DI*DTR];
__device__ __align__(16) bf16 g_wdlo[DI*DTR];
__device__ __align__(16) bf16 g_wohi[DM*DI];
__device__ __align__(16) bf16 g_wolo[DM*DI];
__device__ __align__(16) bf16 g_w1hi[4096*DM];
__device__ __align__(16) bf16 g_w1lo[4096*DM];
__device__ __align__(16) bf16 g_w2hi[DM*4096];
__device__ __align__(16) bf16 g_w2lo[DM*4096];
__device__ __align__(16) bf16 g_uhi[BT*DI];
__device__ __align__(16) bf16 g_ulo[BT*DI];
__device__ __align__(16) bf16 g_xdhi[BT*96];
__device__ __align__(16) bf16 g_xdlo[BT*96];
__device__ __align__(16) bf16 g_yghi[BT*DI];
__device__ __align__(16) bf16 g_yglo[BT*DI];
__device__ __align__(16) bf16 g_mhi[BT*DM];
__device__ __align__(16) bf16 g_mlo[BT*DM];
__device__ __align__(16) bf16 g_ghi[BT*4096];
__device__ __align__(16) bf16 g_glo[BT*4096];

/* ---------------- bf16 split-GEMM via wmma, 3-stage cp.async pipeline ---- */
#define BMT 128
#define BNT 128
#define BKT 32
#define AST 40
#define TILE_E (128*AST)          /* elems per tile  (5120)  */
#define STAGE_E (4*TILE_E)        /* elems per stage (20480) */
#define NSTG 3
#define DSM_BYTES (NSTG*STAGE_E*2) /* 122880 */

/* OP: 1=in_proj 3=x_proj 4=dt_proj 6=out_proj 7=ffn1 8=ffn2 */
template<int OP>
__global__ __launch_bounds__(256)
void wgemm(float* __restrict__ Cext, const float* __restrict__ bias)
{
    constexpr int NN  = (OP==1)?4096 : (OP==3)?96 : (OP==4)?2048 : (OP==6)?1024 : (OP==7)?4096 : 1024;
    constexpr int KK  = (OP==1)?1024 : (OP==3)?2048 : (OP==4)?64 : (OP==6)?2048 : (OP==7)?1024 : 4096;
    constexpr int LDA = (OP==4) ? 96 : KK;
    constexpr int LDB = KK;
    constexpr int LDC = NN;
    constexpr bool WF32   = (OP != 7);
    constexpr bool WSPLIT = (OP==3 || OP==6 || OP==7);

    const bf16* Ahi;
    const bf16* Alo;
    const bf16* Bhw;
    const bf16* Blw;
    float* C = Cext;
    bf16* Chi = 0;
    bf16* Clo = 0;
    if (OP==1) { Ahi=g_xhi;  Alo=g_xlo;  Bhw=g_wihi; Blw=g_wilo; C=g_xz; }
    if (OP==3) { Ahi=g_uhi;  Alo=g_ulo;  Bhw=g_wxhi; Blw=g_wxlo; C=g_xdbl; Chi=g_xdhi; Clo=g_xdlo; }
    if (OP==4) { Ahi=g_xdhi; Alo=g_xdlo; Bhw=g_wdhi; Blw=g_wdlo; C=g_dl; }
    if (OP==6) { Ahi=g_yghi; Alo=g_yglo; Bhw=g_wohi; Blw=g_wolo; C=g_m; Chi=g_mhi; Clo=g_mlo; }
    if (OP==7) { Ahi=g_mhi;  Alo=g_mlo;  Bhw=g_w1hi; Blw=g_w1lo; Chi=g_ghi; Clo=g_glo; }
    if (OP==8) { Ahi=g_ghi;  Alo=g_glo;  Bhw=g_w2hi; Blw=g_w2lo; }

    extern __shared__ bf16 dsm[];
    __shared__ float stage[8][16][16];

    const int tid  = threadIdx.x;
    const int lane = tid & 31;
    const int warp = tid >> 5;
    const int wm   = warp >> 1;
    const int wn   = warp & 1;
    const int bm   = blockIdx.y * BMT;
    const int bn   = blockIdx.x * BNT;
    const int lr   = tid >> 1;            /* 0..127 */
    const int lc   = (tid & 1) * 16;      /* 0 or 16 */

    wmma::fragment<wmma::accumulator, 16, 16, 16, float> acc[2][4];
    for (int mt = 0; mt < 2; mt++)
        for (int nt = 0; nt < 4; nt++)
            wmma::fill_fragment(acc[mt][nt], 0.0f);

    constexpr int nk = KK / BKT;

    const bool bvalid = (bn + lr) < NN;
    const int brow = bvalid ? (bn + lr) : 0;
    const size_t zf = bvalid ? 0 : 16;

    const bf16* gah = Ahi + (size_t)(bm + lr) * LDA + lc;
    const bf16* gal = Alo + (size_t)(bm + lr) * LDA + lc;
    const bf16* gbh = Bhw + (size_t)brow * LDB + lc;
    const bf16* gbl = Blw + (size_t)brow * LDB + lc;
    bf16* const srow = dsm + lr * AST + lc;

    /* prologue: prefetch NSTG-1 stages */
    for (int s = 0; s < NSTG - 1; s++) {
        if (s < nk) {
            int k0 = s * BKT;
            bf16* sb = srow + s * STAGE_E;
            __pipeline_memcpy_async(sb,                        gah + k0,     16);
            __pipeline_memcpy_async(sb + 8,                    gah + k0 + 8, 16);
            __pipeline_memcpy_async(sb + TILE_E,               gal + k0,     16);
            __pipeline_memcpy_async(sb + TILE_E + 8,           gal + k0 + 8, 16);
            __pipeline_memcpy_async(sb + 2 * TILE_E,           gbh + k0,     16, zf);
            __pipeline_memcpy_async(sb + 2 * TILE_E + 8,       gbh + k0 + 8, 16, zf);
            __pipeline_memcpy_async(sb + 3 * TILE_E,           gbl + k0,     16, zf);
            __pipeline_memcpy_async(sb + 3 * TILE_E + 8,       gbl + k0 + 8, 16, zf);
        }
        __pipeline_commit();
    }

    for (int ki = 0; ki < nk; ki++) {
        __pipeline_wait_prior(NSTG - 2);
        __syncthreads();

        /* issue loads for stage ki+NSTG-1 */
        {
            int pre = ki + NSTG - 1;
            if (pre < nk) {
                int k0 = pre * BKT;
                bf16* sb = srow + (pre % NSTG) * STAGE_E;
                __pipeline_memcpy_async(sb,                    gah + k0,     16);
                __pipeline_memcpy_async(sb + 8,                gah + k0 + 8, 16);
                __pipeline_memcpy_async(sb + TILE_E,           gal + k0,     16);
                __pipeline_memcpy_async(sb + TILE_E + 8,       gal + k0 + 8, 16);
                __pipeline_memcpy_async(sb + 2 * TILE_E,       gbh + k0,     16, zf);
                __pipeline_memcpy_async(sb + 2 * TILE_E + 8,   gbh + k0 + 8, 16, zf);
                __pipeline_memcpy_async(sb + 3 * TILE_E,       gbl + k0,     16, zf);
                __pipeline_memcpy_async(sb + 3 * TILE_E + 8,   gbl + k0 + 8, 16, zf);
            }
            __pipeline_commit();
        }

        /* compute on stage ki */
        const bf16* sb = dsm + (ki % NSTG) * STAGE_E;
        for (int kk = 0; kk < BKT; kk += 16) {
            wmma::fragment<wmma::matrix_a, 16, 16, 16, bf16, wmma::row_major> fah[2];
            wmma::fragment<wmma::matrix_a, 16, 16, 16, bf16, wmma::row_major> fal[2];
            for (int mt = 0; mt < 2; mt++) {
                int r = wm * 32 + mt * 16;
                wmma::load_matrix_sync(fah[mt], sb + r * AST + kk, AST);
                wmma::load_matrix_sync(fal[mt], sb + TILE_E + r * AST + kk, AST);
            }
            for (int nt = 0; nt < 4; nt++) {
                int r = wn * 64 + nt * 16;
                wmma::fragment<wmma::matrix_b, 16, 16, 16, bf16, wmma::col_major> fbh;
                wmma::fragment<wmma::matrix_b, 16, 16, 16, bf16, wmma::col_major> fbl;
                wmma::load_matrix_sync(fbh, sb + 2 * TILE_E + r * AST + kk, AST);
                wmma::load_matrix_sync(fbl, sb + 3 * TILE_E + r * AST + kk, AST);
                for (int mt = 0; mt < 2; mt++) {
                    wmma::mma_sync(acc[mt][nt], fah[mt], fbh, acc[mt][nt]);
                    wmma::mma_sync(acc[mt][nt], fah[mt], fbl, acc[mt][nt]);
                    wmma::mma_sync(acc[mt][nt], fal[mt], fbh, acc[mt][nt]);
                }
            }
        }
    }

    /* --- epilogue: stage each 16x16 tile through smem --- */
    for (int mt = 0; mt < 2; mt++) {
        for (int nt = 0; nt < 4; nt++) {
            __syncwarp();
            wmma::store_matrix_sync(&stage[warp][0][0], acc[mt][nt], 16, wmma::mem_row_major);
            __syncwarp();
            for (int i = 0; i < 8; i++) {
                int idx = i * 32 + lane;
                int rr = idx >> 4;
                int cc = idx & 15;
                int grow = bm + wm * 32 + mt * 16 + rr;
                int gcol = bn + wn * 64 + nt * 16 + cc;
                if (gcol < NN) {
                    float v = stage[warp][rr][cc];
                    if (OP == 4) {
                        v += bias[gcol];
                        v = (v > 20.f) ? v : log1pf(__expf(v));
                    }
                    if (OP == 7) {
                        v += bias[gcol];
                        v = 0.5f * v * (1.f + erff(v * 0.70710678118654752f));
                    }
                    if (OP == 8) {
                        v += bias[gcol] + g_m[(size_t)grow * 1024 + gcol];
                    }
                    if (WF32) {
                        C[(size_t)grow * LDC + gcol] = v;
                    }
                    if (WSPLIT) {
                        bf16 h = __float2bfloat16(v);
                        Chi[(size_t)grow * LDC + gcol] = h;
                        Clo[(size_t)grow * LDC + gcol] = __float2bfloat16(v - __bfloat162float(h));
                    }
                }
            }
        }
    }
}

/* ---------------- fp32 -> bf16 hi/lo split ------------------------------- */
/* W: 0=x 1=in_proj 2=x_proj 3=dt_proj 4=out_proj 5=w1 6=w2 */
template<int W>
__global__ void split_kernel(const float4* __restrict__ src, int n4)
{
    bf16* hi;
    bf16* lo;
    if (W==0) { hi=g_xhi;  lo=g_xlo;  }
    if (W==1) { hi=g_wihi; lo=g_wilo; }
    if (W==2) { hi=g_wxhi; lo=g_wxlo; }
    if (W==3) { hi=g_wdhi; lo=g_wdlo; }
    if (W==4) { hi=g_wohi; lo=g_wolo; }
    if (W==5) { hi=g_w1hi; lo=g_w1lo; }
    if (W==6) { hi=g_w2hi; lo=g_w2lo; }

    int i = blockIdx.x * blockDim.x + threadIdx.x;
    if (i >= n4) return;
    float4 v = src[i];
    float vv[4];
    vv[0] = v.x; vv[1] = v.y; vv[2] = v.z; vv[3] = v.w;
    for (int q = 0; q < 4; q++) {
        bf16 h = __float2bfloat16(vv[q]);
        hi[i * 4 + q] = h;
        lo[i * 4 + q] = __float2bfloat16(vv[q] - __bfloat162float(h));
    }
}

/* ---------------- causal depthwise conv (width 4) + SiLU + split --------- */
__global__ void conv_silu_kernel(const float* __restrict__ w,
                                 const float* __restrict__ bias)
{
    int idx = blockIdx.x * blockDim.x + threadIdx.x;
    if (idx >= BT * DI) return;
    int d  = idx & (DI - 1);
    int bt = idx >> 11;
    int t  = bt & (LL - 1);
    size_t row = (size_t)bt * 4096 + d;

    float w0 = w[d * 4 + 0];
    float w1 = w[d * 4 + 1];
    float w2 = w[d * 4 + 2];
    float w3 = w[d * 4 + 3];
    float acc = bias[d];
    if (t >= 3) acc += g_xz[row - 3 * 4096] * w0;
    if (t >= 2) acc += g_xz[row - 2 * 4096] * w1;
    if (t >= 1) acc += g_xz[row - 1 * 4096] * w2;
    acc += g_xz[row] * w3;
    float uv = acc / (1.f + __expf(-acc));
    bf16 h = __float2bfloat16(uv);
    g_uhi[idx] = h;
    g_ulo[idx] = __float2bfloat16(uv - __bfloat162float(h));
}

/* ---------------- selective scan + gate, bf16-split output --------------- */
__global__ __launch_bounds__(128)
void scan_kernel(const float* __restrict__ A_log,
                 const float* __restrict__ Dp)
{
    int d = blockIdx.x * blockDim.x + threadIdx.x;
    int b = blockIdx.y;
    if (d >= DI) return;

    float A[DS];
    for (int n = 0; n < DS; n++) A[n] = -__expf(A_log[d * DS + n]);
    float Dd = Dp[d];

    float h[DS];
    for (int n = 0; n < DS; n++) h[n] = 0.f;

    const float* xd = g_xdbl + (size_t)b * LL * 96;
    size_t base  = (size_t)b * LL * DI + d;
    size_t rbase = (size_t)b * LL * 4096 + DI + d;

    for (int t = 0; t < LL; t++) {
        size_t off = base + (size_t)t * DI;
        float dt  = g_dl[off];
        float ut  = __bfloat162float(g_uhi[off]) + __bfloat162float(g_ulo[off]);
        float res = g_xz[rbase + (size_t)t * 4096];

        const float4* pB = (const float4*)(xd + (size_t)t * 96 + 64);
        const float4* pC = (const float4*)(xd + (size_t)t * 96 + 80);
        float Bv[DS];
        float Cv[DS];
        for (int q = 0; q < 4; q++) {
            float4 bq = pB[q];
            float4 cq = pC[q];
            Bv[q*4+0]=bq.x; Bv[q*4+1]=bq.y; Bv[q*4+2]=bq.z; Bv[q*4+3]=bq.w;
            Cv[q*4+0]=cq.x; Cv[q*4+1]=cq.y; Cv[q*4+2]=cq.z; Cv[q*4+3]=cq.w;
        }

        float y = 0.f;
        for (int n = 0; n < DS; n++) {
            float dA = __expf(dt * A[n]);
            h[n] = dA * h[n] + dt * Bv[n] * ut;
            y = fmaf(h[n], Cv[n], y);
        }
        y += ut * Dd;
        float sres = res / (1.f + __expf(-res));
        float yg = y * sres;
        bf16 hh = __float2bfloat16(yg);
        g_yghi[off] = hh;
        g_yglo[off] = __float2bfloat16(yg - __bfloat162float(hh));
    }
}

/* ---------------- LayerNorm over (seq, d_model) per batch ---------------- */
__global__ void ln_zero_kernel()
{
    if (threadIdx.x < 16) g_sums[threadIdx.x] = 0.f;
}

__global__ void ln_reduce_kernel(const float* __restrict__ c)
{
    int b = blockIdx.y;
    const float4* p = (const float4*)(c + (size_t)b * (LL * DM));
    const int nvec = (LL * DM) / 4;
    float s = 0.f;
    float s2 = 0.f;
    for (int i = blockIdx.x * blockDim.x + threadIdx.x; i < nvec;
         i += gridDim.x * blockDim.x) {
        float4 v = p[i];
        s  += v.x + v.y + v.z + v.w;
        s2 += v.x * v.x + v.y * v.y + v.z * v.z + v.w * v.w;
    }
    __shared__ float ss[256];
    __shared__ float qq[256];
    int tid = threadIdx.x;
    ss[tid] = s;
    qq[tid] = s2;
    __syncthreads();
    for (int o = 128; o > 0; o >>= 1) {
        if (tid < o) {
            ss[tid] += ss[tid + o];
            qq[tid] += qq[tid + o];
        }
        __syncthreads();
    }
    if (tid == 0) {
        atomicAdd(&g_sums[2 * b + 0], ss[0]);
        atomicAdd(&g_sums[2 * b + 1], qq[0]);
    }
}

__global__ void ln_norm_kernel(float* __restrict__ c)
{
    int b = blockIdx.y;
    const float inv_n = 1.f / (float)(LL * DM);
    float mean = g_sums[2 * b + 0] * inv_n;
    float var  = g_sums[2 * b + 1] * inv_n - mean * mean;
    float is   = rsqrtf(var + 1e-5f);
    float4* p = (float4*)(c + (size_t)b * (LL * DM));
    const int nvec = (LL * DM) / 4;
    for (int i = blockIdx.x * blockDim.x + threadIdx.x; i < nvec;
         i += gridDim.x * blockDim.x) {
        float4 v = p[i];
        v.x = (v.x - mean) * is;
        v.y = (v.y - mean) * is;
        v.z = (v.z - mean) * is;
        v.w = (v.w - mean) * is;
        p[i] = v;
    }
}

/* ---------------- host orchestration ------------------------------------ */
extern "C" void kernel_launch(void* const* d_in, const int* in_sizes, int n_in,
                              void* d_out, int out_size)
{
    const float* x         = (const float*)d_in[0];
    const float* in_proj_w = (const float*)d_in[1];
    const float* conv_w    = (const float*)d_in[2];
    const float* conv_b    = (const float*)d_in[3];
    const float* x_proj_w  = (const float*)d_in[4];
    const float* dt_proj_w = (const float*)d_in[5];
    const float* dt_proj_b = (const float*)d_in[6];
    const float* A_log     = (const float*)d_in[7];
    const float* Dp        = (const float*)d_in[8];
    const float* out_proj_w= (const float*)d_in[9];
    const float* ffn_w1    = (const float*)d_in[10];
    const float* ffn_b1    = (const float*)d_in[11];
    const float* ffn_w2    = (const float*)d_in[12];
    const float* ffn_b2    = (const float*)d_in[13];
    float* out = (float*)d_out;

    cudaFuncSetAttribute(wgemm<1>, cudaFuncAttributeMaxDynamicSharedMemorySize, DSM_BYTES);
    cudaFuncSetAttribute(wgemm<3>, cudaFuncAttributeMaxDynamicSharedMemorySize, DSM_BYTES);
    cudaFuncSetAttribute(wgemm<4>, cudaFuncAttributeMaxDynamicSharedMemorySize, DSM_BYTES);
    cudaFuncSetAttribute(wgemm<6>, cudaFuncAttributeMaxDynamicSharedMemorySize, DSM_BYTES);
    cudaFuncSetAttribute(wgemm<7>, cudaFuncAttributeMaxDynamicSharedMemorySize, DSM_BYTES);
    cudaFuncSetAttribute(wgemm<8>, cudaFuncAttributeMaxDynamicSharedMemorySize, DSM_BYTES);

    /* 0. hi/lo splits of input + weights */
    split_kernel<0><<<(BT*DM/4 + 255)/256, 256>>>((const float4*)x, BT*DM/4);
    split_kernel<1><<<(4096*DM/4 + 255)/256, 256>>>((const float4*)in_proj_w, 4096*DM/4);
    split_kernel<2><<<(96*DI/4 + 255)/256, 256>>>((const float4*)x_proj_w, 96*DI/4);
    split_kernel<3><<<(DI*DTR/4 + 255)/256, 256>>>((const float4*)dt_proj_w, DI*DTR/4);
    split_kernel<4><<<(DM*DI/4 + 255)/256, 256>>>((const float4*)out_proj_w, DM*DI/4);
    split_kernel<5><<<(4096*DM/4 + 255)/256, 256>>>((const float4*)ffn_w1, 4096*DM/4);
    split_kernel<6><<<(DM*4096/4 + 255)/256, 256>>>((const float4*)ffn_w2, DM*4096/4);

    /* 1. xz = X @ in_proj_w^T  [8192,4096] */
    wgemm<1><<<dim3(32, 64), 256, DSM_BYTES>>>(0, 0);

    /* 2. u = silu(conv(xm)+b) -> hi/lo */
    conv_silu_kernel<<<(BT * DI) / 256, 256>>>(conv_w, conv_b);

    /* 3. x_dbl = u @ x_proj_w^T  [8192,96] + split */
    wgemm<3><<<dim3(1, 64), 256, DSM_BYTES>>>(0, 0);

    /* 4. delta = softplus(dt @ dt_proj_w^T + b)  [8192,2048] */
    wgemm<4><<<dim3(16, 64), 256, DSM_BYTES>>>(0, dt_proj_b);

    /* 5. selective scan + gate -> yg hi/lo */
    scan_kernel<<<dim3(DI / 128, BB), 128>>>(A_log, Dp);

    /* 6. m = yg @ out_proj_w^T  [8192,1024] + split */
    wgemm<6><<<dim3(8, 64), 256, DSM_BYTES>>>(0, 0);

    /* 7. g = gelu(m @ ffn_w1^T + b1)  [8192,4096] split only */
    wgemm<7><<<dim3(32, 64), 256, DSM_BYTES>>>(0, ffn_b1);

    /* 8. c = m + g @ ffn_w2^T + b2 -> d_out */
    wgemm<8><<<dim3(8, 64), 256, DSM_BYTES>>>(out, ffn_b2);

    /* 9. LayerNorm per batch, in place on d_out */
    ln_zero_kernel<<<1, 32>>>();
    ln_reduce_kernel<<<dim3(128, BB), 256>>>(out);
    ln_norm_kernel<<<dim3(128, BB), 256>>>(out);
}